// round 16
// baseline (speedup 1.0000x reference)
#include <cuda_runtime.h>
#include <cuda_bf16.h>
#include <cstdint>

#define NQ        8192
#define NR        16384
#define KNN       8
#define NCHUNK    64
#define RPC       (NR / NCHUNK)     // 256 refs per chunk
#define PPC       (RPC / 2)         // 128 packed pairs (4 KB tile)
#define QPB       128               // threads per block (p1a)
#define QT        4                 // queries per thread (p1a)
#define QPG       (QPB * QT)        // 512 queries per block
#define QBLK      (NQ / QPG)        // 16 -> grid 1024 for p1a
#define NSL       8                 // slices per chunk (32 refs each)
#define PPSL      (PPC / NSL)       // 16 pairs per slice
#define NSLICES   (NCHUNK * NSL)    // 512 slices total
#define MAXH      28                // hit-slice cap per query
#define MAXK      32                // candidate-key cap per query

typedef unsigned long long ull;

// Slice minima in D^2-SPACE as bf16 (round-down), 2 per uint: 8 MB total.
// d2 = rn(s + q^2) >= 0 (up to proxy rounding) -> bf16 ulp is tiny at the scale
// that matters (d8^2 ~ 0.01), unlike s-space where |s| ~ q^2 ~ 3.
__device__ unsigned g_sminb[(size_t)NQ * (NSLICES / 2)];

__device__ __forceinline__ ull fma2(ull a, ull b, ull c) {
    ull d; asm("fma.rn.f32x2 %0, %1, %2, %3;" : "=l"(d) : "l"(a), "l"(b), "l"(c));
    return d;
}
__device__ __forceinline__ ull pk2(float lo, float hi) {
    ull r; asm("mov.b64 %0, {%1, %2};" : "=l"(r) : "f"(lo), "f"(hi));
    return r;
}
__device__ __forceinline__ void up2(float& lo, float& hi, ull v) {
    asm("mov.b64 {%0, %1}, %2;" : "=f"(lo), "=f"(hi) : "l"(v));
}
__device__ __forceinline__ unsigned f2ord(float f) {
    unsigned b = __float_as_uint(f);
    return (b & 0x80000000u) ? ~b : (b | 0x80000000u);
}
// q^2 with one fixed instruction sequence, used IDENTICALLY in p1a and p1c.
__device__ __forceinline__ float qsq_of(float x, float y, float z) {
    return __fadd_rn(__fadd_rn(__fmul_rn(x, x), __fmul_rn(y, y)), __fmul_rn(z, z));
}

// Stage tile: pack {x01,y01,z01,w01}, w = r^2 (reference rounding, no contraction).
__device__ __forceinline__ void stage_tile(ulonglong4* tile, const float* __restrict__ ref,
                                           int rbase) {
    for (int p = threadIdx.x; p < PPC; p += QPB) {
        const float2* a = (const float2*)(ref + (size_t)(rbase + 2 * p) * 3);
        float2 u0 = __ldg(a), u1 = __ldg(a + 1), u2 = __ldg(a + 2);
        float x0 = u0.x, y0 = u0.y, z0 = u1.x, x1 = u1.y, y1 = u2.x, z1 = u2.y;
        float w0 = qsq_of(x0, y0, z0);
        float w1 = qsq_of(x1, y1, z1);
        ulonglong4 v;
        v.x = pk2(x0, x1); v.y = pk2(y0, y1); v.z = pk2(z0, z1); v.w = pk2(w0, w1);
        tile[p] = v;
    }
}

// p1a: full scan; store bf16_rd(rn(slice_min_s + q^2)) per (query, slice).
__global__ __launch_bounds__(QPB) void knn_p1a(const float* __restrict__ qry,
                                               const float* __restrict__ ref) {
    __shared__ ulonglong4 tile[PPC];
    const int chunk = blockIdx.x % NCHUNK;
    const int qb    = (blockIdx.x / NCHUNK) * QPG + threadIdx.x;
    stage_tile(tile, ref, chunk * RPC);

    ull m2x[QT], m2y[QT], m2z[QT];
    float qsq[QT];
#pragma unroll
    for (int k = 0; k < QT; ++k) {
        int qi = qb + k * QPB;
        float qx = qry[qi * 3 + 0], qy = qry[qi * 3 + 1], qz = qry[qi * 3 + 2];
        m2x[k] = pk2(-2.0f * qx, -2.0f * qx);
        m2y[k] = pk2(-2.0f * qy, -2.0f * qy);
        m2z[k] = pk2(-2.0f * qz, -2.0f * qz);
        qsq[k] = qsq_of(qx, qy, qz);
    }
    const float INF = __int_as_float(0x7f800000);
    float sm[QT][NSL];
    __syncthreads();

#pragma unroll
    for (int sl = 0; sl < NSL; ++sl) {
        float a0[QT], a1[QT];
#pragma unroll
        for (int k = 0; k < QT; ++k) { a0[k] = INF; a1[k] = INF; }
        const ulonglong4* base = tile + sl * PPSL;
#pragma unroll
        for (int it = 0; it < PPSL; ++it) {
            ulonglong4 v = base[it];            // warp-uniform -> LDS broadcast
#pragma unroll
            for (int k = 0; k < QT; ++k) {
                ull s2 = fma2(m2x[k], v.x, fma2(m2y[k], v.y, fma2(m2z[k], v.z, v.w)));
                float s0, s1; up2(s0, s1, s2);
                a0[k] = fminf(a0[k], s0); a1[k] = fminf(a1[k], s1);
            }
        }
#pragma unroll
        for (int k = 0; k < QT; ++k) sm[k][sl] = fminf(a0[k], a1[k]);
    }

    // Shift to d2-space, round DOWN to bf16, pack 8 per (query, chunk).
    // stored <= rn(s_e + q^2) for every element e of the slice (monotone chain).
#pragma unroll
    for (int k = 0; k < QT; ++k) {
        int qi = qb + k * QPB;
        unsigned u[4];
#pragma unroll
        for (int j = 0; j < 4; ++j) {
            float d2a = __fadd_rn(sm[k][2 * j],     qsq[k]);
            float d2b = __fadd_rn(sm[k][2 * j + 1], qsq[k]);
            unsigned lo = (unsigned)__bfloat16_as_ushort(__float2bfloat16_rd(d2a));
            unsigned hi = (unsigned)__bfloat16_as_ushort(__float2bfloat16_rd(d2b));
            u[j] = lo | (hi << 16);
        }
        *(uint4*)(g_sminb + (size_t)qi * (NSLICES / 2) + chunk * 4) =
            make_uint4(u[0], u[1], u[2], u[3]);
    }
}

// p1c: warp per query. tau_d2 from bf16 minima (bitonic-32 + next-up), gate,
// gather hit slices (d2-space test, exact s-space keys), bitonic-32 merge.
__global__ __launch_bounds__(256) void knn_p1c(const float* __restrict__ qry,
                                               const float* __restrict__ ref,
                                               float* __restrict__ out) {
    __shared__ int sh_ids[8][MAXH];
    __shared__ ull sh_keys[8][MAXK];
    const int wid  = threadIdx.x >> 5;
    const int lane = threadIdx.x & 31;
    const int qi   = blockIdx.x * 8 + wid;

    // Load this lane's 16 bf16 slice minima (1 KB/warp, coalesced 2x uint4).
    const unsigned* sb = g_sminb + (size_t)qi * (NSLICES / 2) + lane * 8;
    uint4 va = *(const uint4*)sb;
    uint4 vb = *(const uint4*)(sb + 4);
    unsigned vp[8] = {va.x, va.y, va.z, va.w, vb.x, vb.y, vb.z, vb.w};

    // Per-lane min of 16 bf16 via hmin2 tree.
    __nv_bfloat162 m2 = *(__nv_bfloat162*)&vp[0];
#pragma unroll
    for (int j = 1; j < 8; ++j) m2 = __hmin2(m2, *(__nv_bfloat162*)&vp[j]);
    float pm = fminf(__bfloat162float(__low2bfloat16(m2)),
                     __bfloat162float(__high2bfloat16(m2)));

    // Bitonic-32 ascending; T_d = rank 7; tau = bf16 next-up(T_d) so that
    // exact_value < next_up(stored) <= tau holds for the owning slices.
    float sv = pm;
#pragma unroll
    for (int k = 2; k <= 32; k <<= 1) {
#pragma unroll
        for (int j = k >> 1; j >= 1; j >>= 1) {
            float o = __shfl_xor_sync(0xffffffffu, sv, j);
            bool keepmin = (((lane & j) == 0) == ((lane & k) == 0));
            sv = keepmin ? fminf(sv, o) : fmaxf(sv, o);
        }
    }
    float T_d = __shfl_sync(0xffffffffu, sv, KNN - 1);
    unsigned short tb = __bfloat16_as_ushort(__float2bfloat16_rn(T_d));  // exact
    if (tb & 0x8000) tb = (tb == 0x8000) ? 0x0001 : (unsigned short)(tb - 1);
    else             tb = (unsigned short)(tb + 1);       // value-order next-up
    const float tau = __bfloat162float(__ushort_as_bfloat16(tb));

    // Gate: 16-bit hitmask per lane (d2-space compare), warp scan, compact ids.
    unsigned hm = 0;
#pragma unroll
    for (int j = 0; j < 8; ++j) {
        float2 f = __bfloat1622float2(*(__nv_bfloat162*)&vp[j]);
        hm |= (f.x <= tau) ? (1u << (2 * j)) : 0u;
        hm |= (f.y <= tau) ? (1u << (2 * j + 1)) : 0u;
    }
    int cnt = __popc(hm);
    int inc = cnt;
#pragma unroll
    for (int d = 1; d < 32; d <<= 1) {
        int n = __shfl_up_sync(0xffffffffu, inc, d);
        if (lane >= d) inc += n;
    }
    int slot = inc - cnt;                       // exclusive prefix
    int nhit = __shfl_sync(0xffffffffu, inc, 31);
    unsigned mm = hm;
    while (mm) {
        int b = __ffs(mm) - 1;
        if (slot < MAXH) sh_ids[wid][slot] = lane * 16 + b;
        ++slot;
        mm &= mm - 1;
    }
    if (nhit > MAXH) nhit = MAXH;
    __syncwarp();

    // Query coefficients (scalar; same per-lane rounding as p1a's f32x2).
    const float qx = qry[qi * 3 + 0];
    const float qy = qry[qi * 3 + 1];
    const float qz = qry[qi * 3 + 2];
    const float m2x = -2.0f * qx, m2y = -2.0f * qy, m2z = -2.0f * qz;
    const float qsq = qsq_of(qx, qy, qz);       // bit-equal to p1a's qsq

    // Gather hit slices: d2-space threshold test, exact s-space keys.
    int nk = 0;
    for (int h = 0; h < nhit; ++h) {
        int s = sh_ids[wid][h];
        int ridx = s * 32 + lane;
        const float* rp = ref + (size_t)ridx * 3;
        float x = rp[0], y = rp[1], z = rp[2];
        float w = qsq_of(x, y, z);
        float sd = __fmaf_rn(m2x, x, __fmaf_rn(m2y, y, __fmaf_rn(m2z, z, w)));
        float d2 = __fadd_rn(sd, qsq);
        bool p = (d2 <= tau);
        unsigned m = __ballot_sync(0xffffffffu, p);
        int pre = __popc(m & ((1u << lane) - 1));
        int ks = nk + pre;
        if (p && ks < MAXK)
            sh_keys[wid][ks] = ((ull)f2ord(sd) << 32) | (unsigned)ridx;
        nk += __popc(m);
    }
    if (nk > MAXK) nk = MAXK;
    __syncwarp();

    // Merge: lane j takes key j (pad ~0), bitonic-32 on u64, lanes 0-7 emit.
    ull kv = (lane < nk) ? sh_keys[wid][lane] : ~0ull;
#pragma unroll
    for (int k = 2; k <= 32; k <<= 1) {
#pragma unroll
        for (int j = k >> 1; j >= 1; j >>= 1) {
            ull o = __shfl_xor_sync(0xffffffffu, kv, j);
            bool keepmin = (((lane & j) == 0) == ((lane & k) == 0));
            bool lt = (kv < o);
            kv = (keepmin == lt) ? kv : o;
        }
    }
    if (lane < KNN)
        out[qi * KNN + lane] = (float)(int)(kv & 0xffffffffu);
}

extern "C" void kernel_launch(void* const* d_in, const int* in_sizes, int n_in,
                              void* d_out, int out_size) {
    (void)n_in; (void)out_size;
    const float* q;
    const float* r;
    if (in_sizes[0] < in_sizes[1]) { q = (const float*)d_in[0]; r = (const float*)d_in[1]; }
    else                           { q = (const float*)d_in[1]; r = (const float*)d_in[0]; }

    knn_p1a<<<QBLK * NCHUNK, QPB>>>(q, r);
    knn_p1c<<<NQ / 8, 256>>>(q, r, (float*)d_out);
}

// round 17
// speedup vs baseline: 1.0113x; 1.0113x over previous
#include <cuda_runtime.h>
#include <cstdint>

#define NQ        8192
#define NR        16384
#define KNN       8
#define NCHUNK    128
#define RPC       (NR / NCHUNK)     // 128 refs per chunk
#define PPC       (RPC / 2)         // 64 packed pairs (2 KB tile)
#define QPB       128               // threads per block (p1a)
#define QT        8                 // queries per thread (p1a)
#define QPG       (QPB * QT)        // 1024 queries per block
#define QBLK      (NQ / QPG)        // 8 -> grid 1024 for p1a
#define NSL       4                 // slices per chunk (32 refs each)
#define PPSL      (PPC / NSL)       // 16 pairs per slice
#define NSLICES   (NCHUNK * NSL)    // 512 slices total
#define MAXH      28                // hit-slice cap per query
#define MAXK      32                // candidate-key cap per query

typedef unsigned long long ull;

__device__ float g_smin[(size_t)NQ * NSLICES];   // per (query, slice) minima, 16 MB

__device__ __forceinline__ ull fma2(ull a, ull b, ull c) {
    ull d; asm("fma.rn.f32x2 %0, %1, %2, %3;" : "=l"(d) : "l"(a), "l"(b), "l"(c));
    return d;
}
__device__ __forceinline__ ull pk2(float lo, float hi) {
    ull r; asm("mov.b64 %0, {%1, %2};" : "=l"(r) : "f"(lo), "f"(hi));
    return r;
}
__device__ __forceinline__ void up2(float& lo, float& hi, ull v) {
    asm("mov.b64 {%0, %1}, %2;" : "=f"(lo), "=f"(hi) : "l"(v));
}
__device__ __forceinline__ unsigned f2ord(float f) {
    unsigned b = __float_as_uint(f);
    return (b & 0x80000000u) ? ~b : (b | 0x80000000u);
}

// Stage tile: pack {x01,y01,z01,w01}, w = r^2 (reference rounding, no contraction).
__device__ __forceinline__ void stage_tile(ulonglong4* tile, const float* __restrict__ ref,
                                           int rbase) {
    for (int p = threadIdx.x; p < PPC; p += QPB) {
        const float2* a = (const float2*)(ref + (size_t)(rbase + 2 * p) * 3);
        float2 u0 = __ldg(a), u1 = __ldg(a + 1), u2 = __ldg(a + 2);
        float x0 = u0.x, y0 = u0.y, z0 = u1.x, x1 = u1.y, y1 = u2.x, z1 = u2.y;
        float w0 = __fadd_rn(__fadd_rn(__fmul_rn(x0, x0), __fmul_rn(y0, y0)), __fmul_rn(z0, z0));
        float w1 = __fadd_rn(__fadd_rn(__fmul_rn(x1, x1), __fmul_rn(y1, y1)), __fmul_rn(z1, z1));
        ulonglong4 v;
        v.x = pk2(x0, x1); v.y = pk2(y0, y1); v.z = pk2(z0, z1); v.w = pk2(w0, w1);
        tile[p] = v;
    }
}

// p1a: full scan; store the min of every 32-ref slice per query.
// QT=8 independent query chains per thread -> high ILP hides LDS/FMA latency.
__global__ __launch_bounds__(QPB) void knn_p1a(const float* __restrict__ qry,
                                               const float* __restrict__ ref) {
    __shared__ ulonglong4 tile[PPC];
    const int chunk = blockIdx.x % NCHUNK;
    const int qb    = (blockIdx.x / NCHUNK) * QPG + threadIdx.x;
    stage_tile(tile, ref, chunk * RPC);

    ull m2x[QT], m2y[QT], m2z[QT];
#pragma unroll
    for (int k = 0; k < QT; ++k) {
        int qi = qb + k * QPB;
        float qx = qry[qi * 3 + 0], qy = qry[qi * 3 + 1], qz = qry[qi * 3 + 2];
        m2x[k] = pk2(-2.0f * qx, -2.0f * qx);
        m2y[k] = pk2(-2.0f * qy, -2.0f * qy);
        m2z[k] = pk2(-2.0f * qz, -2.0f * qz);
    }
    const float INF = __int_as_float(0x7f800000);
    float sm[QT][NSL];
    __syncthreads();

#pragma unroll
    for (int sl = 0; sl < NSL; ++sl) {
        float a0[QT], a1[QT];
#pragma unroll
        for (int k = 0; k < QT; ++k) { a0[k] = INF; a1[k] = INF; }
        const ulonglong4* base = tile + sl * PPSL;
#pragma unroll
        for (int it = 0; it < PPSL; ++it) {
            ulonglong4 v = base[it];            // warp-uniform -> LDS broadcast
#pragma unroll
            for (int k = 0; k < QT; ++k) {
                ull s2 = fma2(m2x[k], v.x, fma2(m2y[k], v.y, fma2(m2z[k], v.z, v.w)));
                float s0, s1; up2(s0, s1, s2);
                a0[k] = fminf(a0[k], s0); a1[k] = fminf(a1[k], s1);
            }
        }
#pragma unroll
        for (int k = 0; k < QT; ++k) sm[k][sl] = fminf(a0[k], a1[k]);
    }

#pragma unroll
    for (int k = 0; k < QT; ++k) {
        int qi = qb + k * QPB;
        *(float4*)(g_smin + (size_t)qi * NSLICES + chunk * NSL) =
            make_float4(sm[k][0], sm[k][1], sm[k][2], sm[k][3]);
    }
}

// p1c: warp per query. tau = 8th-smallest per-lane slice-min (bitonic-32),
// bitmask+scan gate, gather hit slices, bitonic-32 merge of keys, write top-8.
__global__ __launch_bounds__(256) void knn_p1c(const float* __restrict__ qry,
                                               const float* __restrict__ ref,
                                               float* __restrict__ out) {
    __shared__ int sh_ids[8][MAXH];
    __shared__ ull sh_keys[8][MAXK];
    const int wid  = threadIdx.x >> 5;
    const int lane = threadIdx.x & 31;
    const int qi   = blockIdx.x * 8 + wid;

    // Load this lane's 16 slice minima (2 KB/warp, coalesced float4).
    const float4* sp = (const float4*)(g_smin + (size_t)qi * NSLICES + lane * 16);
    float v[16];
#pragma unroll
    for (int i = 0; i < 4; ++i) {
        float4 f = sp[i];
        v[i * 4 + 0] = f.x; v[i * 4 + 1] = f.y; v[i * 4 + 2] = f.z; v[i * 4 + 3] = f.w;
    }

    // Per-lane min of 16 (15 fmin).
    float pm = v[0];
#pragma unroll
    for (int j = 1; j < 16; ++j) pm = fminf(pm, v[j]);

    // Bitonic sort of 32 per-lane minima across lanes (ascending); tau = rank 7.
    // Conservative gate: 8 smallest per-lane minima = 8 distinct slices
    // = 8 distinct elements <= tau  =>  tau >= true 8th-smallest distance.
    float sv = pm;
#pragma unroll
    for (int k = 2; k <= 32; k <<= 1) {
#pragma unroll
        for (int j = k >> 1; j >= 1; j >>= 1) {
            float o = __shfl_xor_sync(0xffffffffu, sv, j);
            bool keepmin = (((lane & j) == 0) == ((lane & k) == 0));
            sv = keepmin ? fminf(sv, o) : fmaxf(sv, o);
        }
    }
    const float tau = __shfl_sync(0xffffffffu, sv, KNN - 1);

    // Gate: 16-bit hitmask per lane, warp scan, compact slice ids to smem.
    unsigned hm = 0;
#pragma unroll
    for (int j = 0; j < 16; ++j) hm |= (v[j] <= tau) ? (1u << j) : 0u;
    int cnt = __popc(hm);
    int inc = cnt;
#pragma unroll
    for (int d = 1; d < 32; d <<= 1) {
        int n = __shfl_up_sync(0xffffffffu, inc, d);
        if (lane >= d) inc += n;
    }
    int slot = inc - cnt;                       // exclusive prefix
    int nhit = __shfl_sync(0xffffffffu, inc, 31);
    unsigned mm = hm;
    while (mm) {
        int b = __ffs(mm) - 1;
        if (slot < MAXH) sh_ids[wid][slot] = lane * 16 + b;
        ++slot;
        mm &= mm - 1;
    }
    if (nhit > MAXH) nhit = MAXH;
    __syncwarp();

    // Query coefficients (scalar; bit-identical rounding to p1a's f32x2 lanes).
    const float qx = qry[qi * 3 + 0];
    const float qy = qry[qi * 3 + 1];
    const float qz = qry[qi * 3 + 2];
    const float m2x = -2.0f * qx, m2y = -2.0f * qy, m2z = -2.0f * qz;

    // Gather hit slices: 1 ref per lane per slice; collect keys with s <= tau.
    int nk = 0;
    for (int h = 0; h < nhit; ++h) {
        int s = sh_ids[wid][h];
        int ridx = s * 32 + lane;
        const float* rp = ref + (size_t)ridx * 3;
        float x = rp[0], y = rp[1], z = rp[2];
        float w = __fadd_rn(__fadd_rn(__fmul_rn(x, x), __fmul_rn(y, y)), __fmul_rn(z, z));
        float sd = __fmaf_rn(m2x, x, __fmaf_rn(m2y, y, __fmaf_rn(m2z, z, w)));
        bool p = (sd <= tau);
        unsigned m = __ballot_sync(0xffffffffu, p);
        int pre = __popc(m & ((1u << lane) - 1));
        int ks = nk + pre;
        if (p && ks < MAXK)
            sh_keys[wid][ks] = ((ull)f2ord(sd) << 32) | (unsigned)ridx;
        nk += __popc(m);
    }
    if (nk > MAXK) nk = MAXK;
    __syncwarp();

    // Merge: lane j takes key j (pad ~0), bitonic-32 sort on u64, lanes 0-7 emit.
    ull kv = (lane < nk) ? sh_keys[wid][lane] : ~0ull;
#pragma unroll
    for (int k = 2; k <= 32; k <<= 1) {
#pragma unroll
        for (int j = k >> 1; j >= 1; j >>= 1) {
            ull o = __shfl_xor_sync(0xffffffffu, kv, j);
            bool keepmin = (((lane & j) == 0) == ((lane & k) == 0));
            bool lt = (kv < o);
            kv = (keepmin == lt) ? kv : o;
        }
    }
    if (lane < KNN)
        out[qi * KNN + lane] = (float)(int)(kv & 0xffffffffu);
}

extern "C" void kernel_launch(void* const* d_in, const int* in_sizes, int n_in,
                              void* d_out, int out_size) {
    (void)n_in; (void)out_size;
    const float* q;
    const float* r;
    if (in_sizes[0] < in_sizes[1]) { q = (const float*)d_in[0]; r = (const float*)d_in[1]; }
    else                           { q = (const float*)d_in[1]; r = (const float*)d_in[0]; }

    knn_p1a<<<QBLK * NCHUNK, QPB>>>(q, r);
    knn_p1c<<<NQ / 8, 256>>>(q, r, (float*)d_out);
}